// round 9
// baseline (speedup 1.0000x reference)
#include <cuda_runtime.h>

// Shape: a, b, h : (B=2, S=2048, D=1024, N=16) fp32, row-major.
// h[t] = a[t]*h[t-1] + b[t] along S. B*D*N = 32768 independent channels,
// contiguous at fixed t; scan stride = D*N = 16384 floats.
//
// R8: stack BOTH prefetch paths on top of the R6 demand pipeline:
//   - cp.async.bulk.prefetch.L2.global (TMA-class engine), lead ~22 groups,
//     one elected thread per block, 256 B block-slice per timestep/tensor
//   - prefetch.global.L2 per-line hints (LSU path), lead ~12 groups
//   - demand __ldcs register pipeline, U=8 / distance 4 (L2 hits)
// block=64 / grid=512 so all 148 SMs are covered.

static constexpr int S_LEN   = 2048;
static constexpr int STRIDE  = 1024 * 16;       // D*N floats between timesteps
static constexpr int CHANNELS = 2 * STRIDE;     // 32768
static constexpr int U       = 8;               // timesteps per group
static constexpr int N_GROUPS = S_LEN / U;      // 256
static constexpr int N_SUPER  = N_GROUPS / 8;   // 32 super-iterations
static constexpr int BLOCK   = 64;
static constexpr int PF_G    = 12;              // line-prefetch lead base (groups)
static constexpr int BPF_G   = 22;              // bulk-prefetch lead base (groups)
static constexpr int SLICE_B = BLOCK * 4;       // 256 B contiguous per block/timestep

// Demand-load local group G (relative to current ap/bp) into buffers A/B.
#define PREF(A, B, G)                                            \
    _Pragma("unroll")                                            \
    for (int u = 0; u < U; u++) {                                \
        A[u] = __ldcs(ap + ((G) * U + u) * STRIDE);              \
        B[u] = __ldcs(bp + ((G) * U + u) * STRIDE);              \
    }

// Consume buffers A/B as local group G: serial FMA chain + streaming stores.
#define CONS(A, B, G)                                            \
    _Pragma("unroll")                                            \
    for (int u = 0; u < U; u++) {                                \
        h = fmaf(A[u], h, B[u]);                                 \
        __stcs(op + ((G) * U + u) * STRIDE, h);                  \
    }

// Per-line L2 prefetch of local group G (every thread, own channel).
#define PFL2(G)                                                  \
    if ((s * 8 + (G)) < N_GROUPS) {                              \
        _Pragma("unroll")                                        \
        for (int u = 0; u < U; u++) {                            \
            asm volatile("prefetch.global.L2 [%0];" ::           \
                "l"(pfa + (((G) - PF_G) * U + u) * STRIDE));     \
            asm volatile("prefetch.global.L2 [%0];" ::           \
                "l"(pfb + (((G) - PF_G) * U + u) * STRIDE));     \
        }                                                        \
    }

// Bulk L2 prefetch of local group G (elected thread, 256 B block slice).
#define PFBULK(G)                                                           \
    if (lead && (s * 8 + (G)) < N_GROUPS) {                                 \
        _Pragma("unroll")                                                   \
        for (int u = 0; u < U; u++) {                                       \
            asm volatile("cp.async.bulk.prefetch.L2.global [%0], %1;" ::    \
                "l"(pfa_g + (unsigned long long)(((G) - BPF_G) * U + u) *   \
                            (STRIDE * 4ull)), "r"(SLICE_B));                \
            asm volatile("cp.async.bulk.prefetch.L2.global [%0], %1;" ::    \
                "l"(pfb_g + (unsigned long long)(((G) - BPF_G) * U + u) *   \
                            (STRIDE * 4ull)), "r"(SLICE_B));                \
        }                                                                   \
    }

__global__ __launch_bounds__(BLOCK, 4)
void ParallelScan_37374805409922_kernel(const float* __restrict__ a,
                                        const float* __restrict__ b,
                                        float* __restrict__ out) {
    const int idx   = blockIdx.x * BLOCK + threadIdx.x;        // 0..32767
    const int batch = idx >> 14;                               // / 16384
    const int col   = idx & (STRIDE - 1);
    const size_t base = (size_t)batch * S_LEN * STRIDE + col;

    const float* __restrict__ ap = a + base;
    const float* __restrict__ bp = b + base;
    float* __restrict__ op = out + base;

    // Line-prefetch pointers, pre-advanced by PF_G groups.
    const float* pfa = ap + PF_G * U * STRIDE;
    const float* pfb = bp + PF_G * U * STRIDE;

    // Bulk-prefetch base: block slice (thread 0's channel), pre-advanced by
    // BPF_G groups; global address space.
    const bool lead = (threadIdx.x == 0);
    const int blk_col = (blockIdx.x * BLOCK) & (STRIDE - 1);
    const size_t blk_base = (size_t)((blockIdx.x * BLOCK) >> 14) * S_LEN * STRIDE
                          + blk_col + (size_t)BPF_G * U * STRIDE;
    unsigned long long pfa_g = (unsigned long long)__cvta_generic_to_global(a + blk_base);
    unsigned long long pfb_g = (unsigned long long)__cvta_generic_to_global(b + blk_base);

    float a0[U], b0[U], a1[U], b1[U], a2[U], b2[U], a3[U], b3[U];
    float a4[U], b4[U], a5[U], b5[U], a6[U], b6[U], a7[U], b7[U];
    float h = 0.0f;

    // Prologue: bulk-cover groups [PF_G, BPF_G) so the line-prefetch window
    // always lands on L2-bound data, then demand-load 4 groups.
    if (lead) {
        #pragma unroll 1
        for (int t = PF_G * U; t < BPF_G * U; t++) {
            asm volatile("cp.async.bulk.prefetch.L2.global [%0], %1;" ::
                "l"(pfa_g + (unsigned long long)(t - BPF_G * U) * (STRIDE * 4ull)),
                "r"(SLICE_B));
            asm volatile("cp.async.bulk.prefetch.L2.global [%0], %1;" ::
                "l"(pfb_g + (unsigned long long)(t - BPF_G * U) * (STRIDE * 4ull)),
                "r"(SLICE_B));
        }
    }
    PREF(a0, b0, 0)
    PREF(a1, b1, 1)
    PREF(a2, b2, 2)
    PREF(a3, b3, 3)

    #pragma unroll 1
    for (int s = 0; s < N_SUPER; s++) {
        // Each slot: bulk-prefetch ~22 groups ahead, line-prefetch ~12 ahead,
        // demand-load 4 ahead, consume current.
        PFBULK(22)  PFL2(12)  PREF(a4, b4, 4)  CONS(a0, b0, 0)
        PFBULK(23)  PFL2(13)  PREF(a5, b5, 5)  CONS(a1, b1, 1)
        PFBULK(24)  PFL2(14)  PREF(a6, b6, 6)  CONS(a2, b2, 2)
        PFBULK(25)  PFL2(15)  PREF(a7, b7, 7)  CONS(a3, b3, 3)

        if (s + 1 < N_SUPER) {
            PFBULK(26)  PFL2(16)  PREF(a0, b0, 8)   CONS(a4, b4, 4)
            PFBULK(27)  PFL2(17)  PREF(a1, b1, 9)   CONS(a5, b5, 5)
            PFBULK(28)  PFL2(18)  PREF(a2, b2, 10)  CONS(a6, b6, 6)
            PFBULK(29)  PFL2(19)  PREF(a3, b3, 11)  CONS(a7, b7, 7)
        } else {
            CONS(a4, b4, 4)
            CONS(a5, b5, 5)
            CONS(a6, b6, 6)
            CONS(a7, b7, 7)
        }

        ap    += 8 * U * STRIDE;
        bp    += 8 * U * STRIDE;
        op    += 8 * U * STRIDE;
        pfa   += 8 * U * STRIDE;
        pfb   += 8 * U * STRIDE;
        pfa_g += 8ull * U * STRIDE * 4ull;
        pfb_g += 8ull * U * STRIDE * 4ull;
    }
}

extern "C" void kernel_launch(void* const* d_in, const int* in_sizes, int n_in,
                              void* d_out, int out_size) {
    const float* a = (const float*)d_in[0];
    const float* b = (const float*)d_in[1];
    float* out = (float*)d_out;
    (void)in_sizes; (void)n_in; (void)out_size;

    ParallelScan_37374805409922_kernel<<<CHANNELS / BLOCK, BLOCK>>>(a, b, out);
}

// round 10
// speedup vs baseline: 1.2111x; 1.2111x over previous
#include <cuda_runtime.h>

// Shape: a, b, h : (B=2, S=2048, D=1024, N=16) fp32, row-major.
// h[t] = a[t]*h[t-1] + b[t] along S. B*D*N = 32768 independent channels,
// contiguous at fixed t; scan stride = D*N = 16384 floats.
//
// R9: R6 base (best known: block=64/grid=512, U=8/distance-4 demand register
// pipeline, prefetch.global.L2 at lead ~12 groups) + a SECOND re-hint pass at
// lead ~6 groups. prefetch.global.L2 is a droppable hint; dropped lines fall
// into the saturated (~68%-capable) demand-miss path. Re-hinting gives each
// line two independent chances -> higher prefetch coverage -> higher DRAM%.

static constexpr int S_LEN   = 2048;
static constexpr int STRIDE  = 1024 * 16;       // D*N floats between timesteps
static constexpr int CHANNELS = 2 * STRIDE;     // 32768
static constexpr int U       = 8;               // timesteps per group
static constexpr int N_GROUPS = S_LEN / U;      // 256
static constexpr int N_SUPER  = N_GROUPS / 8;   // 32 super-iterations
static constexpr int BLOCK   = 64;
static constexpr int PF_G    = 12;              // primary prefetch lead (groups)
static constexpr int RE_G    = 6;               // re-hint lead (groups)

// Demand-load local group G (relative to current ap/bp) into buffers A/B.
#define PREF(A, B, G)                                            \
    _Pragma("unroll")                                            \
    for (int u = 0; u < U; u++) {                                \
        A[u] = __ldcs(ap + ((G) * U + u) * STRIDE);              \
        B[u] = __ldcs(bp + ((G) * U + u) * STRIDE);              \
    }

// Consume buffers A/B as local group G: serial FMA chain + streaming stores.
#define CONS(A, B, G)                                            \
    _Pragma("unroll")                                            \
    for (int u = 0; u < U; u++) {                                \
        h = fmaf(A[u], h, B[u]);                                 \
        __stcs(op + ((G) * U + u) * STRIDE, h);                  \
    }

// Primary per-line L2 prefetch of local group G (pfa/pfb pre-advanced PF_G).
#define PFL2(G)                                                  \
    if ((s * 8 + (G)) < N_GROUPS) {                              \
        _Pragma("unroll")                                        \
        for (int u = 0; u < U; u++) {                            \
            asm volatile("prefetch.global.L2 [%0];" ::           \
                "l"(pfa + (((G) - PF_G) * U + u) * STRIDE));     \
            asm volatile("prefetch.global.L2 [%0];" ::           \
                "l"(pfb + (((G) - PF_G) * U + u) * STRIDE));     \
        }                                                        \
    }

// Re-hint pass of local group G (ra/rb pre-advanced RE_G): second chance for
// lines whose primary hint was dropped.
#define REL2(G)                                                  \
    if ((s * 8 + (G)) < N_GROUPS) {                              \
        _Pragma("unroll")                                        \
        for (int u = 0; u < U; u++) {                            \
            asm volatile("prefetch.global.L2 [%0];" ::           \
                "l"(ra + (((G) - RE_G) * U + u) * STRIDE));      \
            asm volatile("prefetch.global.L2 [%0];" ::           \
                "l"(rb + (((G) - RE_G) * U + u) * STRIDE));      \
        }                                                        \
    }

__global__ __launch_bounds__(BLOCK, 4)
void ParallelScan_37374805409922_kernel(const float* __restrict__ a,
                                        const float* __restrict__ b,
                                        float* __restrict__ out) {
    const int idx   = blockIdx.x * BLOCK + threadIdx.x;        // 0..32767
    const int batch = idx >> 14;                               // / 16384
    const int col   = idx & (STRIDE - 1);
    const size_t base = (size_t)batch * S_LEN * STRIDE + col;

    const float* __restrict__ ap = a + base;
    const float* __restrict__ bp = b + base;
    float* __restrict__ op = out + base;

    const float* pfa = ap + PF_G * U * STRIDE;
    const float* pfb = bp + PF_G * U * STRIDE;
    const float* ra  = ap + RE_G * U * STRIDE;
    const float* rb  = bp + RE_G * U * STRIDE;

    float a0[U], b0[U], a1[U], b1[U], a2[U], b2[U], a3[U], b3[U];
    float a4[U], b4[U], a5[U], b5[U], a6[U], b6[U], a7[U], b7[U];
    float h = 0.0f;

    // Prologue: demand-load 4 groups (prefetch windows warm up organically).
    PREF(a0, b0, 0)
    PREF(a1, b1, 1)
    PREF(a2, b2, 2)
    PREF(a3, b3, 3)

    #pragma unroll 1
    for (int s = 0; s < N_SUPER; s++) {
        // Each slot: primary hint 12 groups ahead, re-hint 6 ahead,
        // demand-load 4 ahead, consume current.
        PFL2(12)  REL2(6)   PREF(a4, b4, 4)  CONS(a0, b0, 0)
        PFL2(13)  REL2(7)   PREF(a5, b5, 5)  CONS(a1, b1, 1)
        PFL2(14)  REL2(8)   PREF(a6, b6, 6)  CONS(a2, b2, 2)
        PFL2(15)  REL2(9)   PREF(a7, b7, 7)  CONS(a3, b3, 3)

        if (s + 1 < N_SUPER) {
            PFL2(16)  REL2(10)  PREF(a0, b0, 8)   CONS(a4, b4, 4)
            PFL2(17)  REL2(11)  PREF(a1, b1, 9)   CONS(a5, b5, 5)
            PFL2(18)  REL2(12)  PREF(a2, b2, 10)  CONS(a6, b6, 6)
            PFL2(19)  REL2(13)  PREF(a3, b3, 11)  CONS(a7, b7, 7)
        } else {
            CONS(a4, b4, 4)
            CONS(a5, b5, 5)
            CONS(a6, b6, 6)
            CONS(a7, b7, 7)
        }

        ap  += 8 * U * STRIDE;
        bp  += 8 * U * STRIDE;
        op  += 8 * U * STRIDE;
        pfa += 8 * U * STRIDE;
        pfb += 8 * U * STRIDE;
        ra  += 8 * U * STRIDE;
        rb  += 8 * U * STRIDE;
    }
}

extern "C" void kernel_launch(void* const* d_in, const int* in_sizes, int n_in,
                              void* d_out, int out_size) {
    const float* a = (const float*)d_in[0];
    const float* b = (const float*)d_in[1];
    float* out = (float*)d_out;
    (void)in_sizes; (void)n_in; (void)out_size;

    ParallelScan_37374805409922_kernel<<<CHANNELS / BLOCK, BLOCK>>>(a, b, out);
}

// round 11
// speedup vs baseline: 1.3744x; 1.1349x over previous
#include <cuda_runtime.h>

// Shape: a, b, h : (B=2, S=2048, D=1024, N=16) fp32, row-major.
// h[t] = a[t]*h[t-1] + b[t] along S. B*D*N = 32768 independent channels,
// contiguous at fixed t; scan stride = D*N = 16384 floats.
//
// R10: best mechanism x best shape.
//   mechanism (R6): demand __ldcs register pipeline U=8 / distance 4 +
//     single-pass per-line prefetch.global.L2 at lead 12 groups
//     (ncu-measured 123 us, DRAM 77% — ceiling for this path)
//   shape (R7): block=256 / grid=128 — smallest wall-vs-ncu replay gap
//     (3.6 us vs 14.6 us for block=64/grid=512 in the harness's
//     back-to-back graph-replay regime with dirty L2)

static constexpr int S_LEN   = 2048;
static constexpr int STRIDE  = 1024 * 16;       // D*N floats between timesteps
static constexpr int CHANNELS = 2 * STRIDE;     // 32768
static constexpr int U       = 8;               // timesteps per group
static constexpr int N_GROUPS = S_LEN / U;      // 256
static constexpr int N_SUPER  = N_GROUPS / 8;   // 32 super-iterations
static constexpr int BLOCK   = 256;
static constexpr int PF_G    = 12;              // prefetch lead base (groups)

// Demand-load local group G (relative to current ap/bp) into buffers A/B.
#define PREF(A, B, G)                                            \
    _Pragma("unroll")                                            \
    for (int u = 0; u < U; u++) {                                \
        A[u] = __ldcs(ap + ((G) * U + u) * STRIDE);              \
        B[u] = __ldcs(bp + ((G) * U + u) * STRIDE);              \
    }

// Consume buffers A/B as local group G: serial FMA chain + streaming stores.
#define CONS(A, B, G)                                            \
    _Pragma("unroll")                                            \
    for (int u = 0; u < U; u++) {                                \
        h = fmaf(A[u], h, B[u]);                                 \
        __stcs(op + ((G) * U + u) * STRIDE, h);                  \
    }

// Per-line L2 prefetch of local group G (pfa/pfb pre-advanced by PF_G groups).
#define PFL2(G)                                                  \
    if ((s * 8 + (G)) < N_GROUPS) {                              \
        _Pragma("unroll")                                        \
        for (int u = 0; u < U; u++) {                            \
            asm volatile("prefetch.global.L2 [%0];" ::           \
                "l"(pfa + (((G) - PF_G) * U + u) * STRIDE));     \
            asm volatile("prefetch.global.L2 [%0];" ::           \
                "l"(pfb + (((G) - PF_G) * U + u) * STRIDE));     \
        }                                                        \
    }

__global__ __launch_bounds__(BLOCK, 1)
void ParallelScan_37374805409922_kernel(const float* __restrict__ a,
                                        const float* __restrict__ b,
                                        float* __restrict__ out) {
    const int idx   = blockIdx.x * BLOCK + threadIdx.x;        // 0..32767
    const int batch = idx >> 14;                               // / 16384
    const int col   = idx & (STRIDE - 1);
    const size_t base = (size_t)batch * S_LEN * STRIDE + col;

    const float* __restrict__ ap = a + base;
    const float* __restrict__ bp = b + base;
    float* __restrict__ op = out + base;

    const float* pfa = ap + PF_G * U * STRIDE;
    const float* pfb = bp + PF_G * U * STRIDE;

    float a0[U], b0[U], a1[U], b1[U], a2[U], b2[U], a3[U], b3[U];
    float a4[U], b4[U], a5[U], b5[U], a6[U], b6[U], a7[U], b7[U];
    float h = 0.0f;

    // Prologue: demand-load 4 groups (prefetch window warms up organically).
    PREF(a0, b0, 0)
    PREF(a1, b1, 1)
    PREF(a2, b2, 2)
    PREF(a3, b3, 3)

    #pragma unroll 1
    for (int s = 0; s < N_SUPER; s++) {
        // Each slot: L2-prefetch 12 groups ahead, demand-load 4 ahead,
        // consume current.
        PFL2(12)  PREF(a4, b4, 4)  CONS(a0, b0, 0)
        PFL2(13)  PREF(a5, b5, 5)  CONS(a1, b1, 1)
        PFL2(14)  PREF(a6, b6, 6)  CONS(a2, b2, 2)
        PFL2(15)  PREF(a7, b7, 7)  CONS(a3, b3, 3)

        if (s + 1 < N_SUPER) {
            PFL2(16)  PREF(a0, b0, 8)   CONS(a4, b4, 4)
            PFL2(17)  PREF(a1, b1, 9)   CONS(a5, b5, 5)
            PFL2(18)  PREF(a2, b2, 10)  CONS(a6, b6, 6)
            PFL2(19)  PREF(a3, b3, 11)  CONS(a7, b7, 7)
        } else {
            CONS(a4, b4, 4)
            CONS(a5, b5, 5)
            CONS(a6, b6, 6)
            CONS(a7, b7, 7)
        }

        ap  += 8 * U * STRIDE;
        bp  += 8 * U * STRIDE;
        op  += 8 * U * STRIDE;
        pfa += 8 * U * STRIDE;
        pfb += 8 * U * STRIDE;
    }
}

extern "C" void kernel_launch(void* const* d_in, const int* in_sizes, int n_in,
                              void* d_out, int out_size) {
    const float* a = (const float*)d_in[0];
    const float* b = (const float*)d_in[1];
    float* out = (float*)d_out;
    (void)in_sizes; (void)n_in; (void)out_size;

    ParallelScan_37374805409922_kernel<<<CHANNELS / BLOCK, BLOCK>>>(a, b, out);
}